// round 3
// baseline (speedup 1.0000x reference)
#include <cuda_runtime.h>
#include <cuda_bf16.h>

// EmbeddingsAverage: out[b,o] = (sum_{t<len[b]} x[b,t,:] / len[b]) . W[o,:] + bias[o]
// x: [64, 2048, 1024] f32, lengths: [64] i64-or-i32, W: [8, 1024] f32, bias: [8] f32
// out: [64, 8] f32
// Single launch: split-T partial sums, per-block projection onto W, and a
// fence+counter "last block per batch" epilogue that finalizes out[b].

#define Bq   64
#define Tq   2048
#define Dq   1024
#define OUTq 8
#define SPLITS 32
#define ROWS (Tq / SPLITS)   // 64 time rows per split
#define THREADS 256          // 256 * float4 = 1024 = D

// Projected partials per (b, split, out): 64*32*8*4B = 64 KB (L2-resident).
__device__ float g_pout[Bq * SPLITS * OUTq];
// Per-batch completion counters (zero-initialized at module load; the last
// block resets its counter to 0 so graph replays start clean).
__device__ unsigned g_count[Bq];

// lengths dtype detection: if int64 (little-endian), word[1] is the high word
// of lengths[0] == 0 (lengths <= 2048). If int32, word[1] == lengths[1] >= 1.
__device__ __forceinline__ int load_len(const void* lenp, int b) {
    const unsigned* u = (const unsigned*)lenp;
    if (u[1] == 0u) {
        return (int)u[2 * b];            // int64 layout: low word at 2*b
    } else {
        return (int)((const int*)lenp)[b];
    }
}

__global__ void __launch_bounds__(THREADS)
fused_kernel(const float* __restrict__ x,
             const void* __restrict__ lenp,
             const float* __restrict__ W,
             const float* __restrict__ bias,
             float* __restrict__ out) {
    const int b = blockIdx.x;
    const int s = blockIdx.y;
    const int tid = threadIdx.x;
    const int lane = tid & 31;
    const int warp = tid >> 5;
    const int rowstride = Dq / 4;        // float4 units per time row

    const int len = load_len(lenp, b);
    const int t0 = s * ROWS;
    const int n  = min(t0 + ROWS, len) - t0;   // may be <= 0

    float4 acc = make_float4(0.f, 0.f, 0.f, 0.f);

    const float4* __restrict__ xp =
        (const float4*)(x + ((long long)b * Tq + t0) * Dq) + tid;

    int t = 0;
    for (; t + 4 <= n; t += 4) {
        float4 a0 = xp[(t + 0) * rowstride];
        float4 a1 = xp[(t + 1) * rowstride];
        float4 a2 = xp[(t + 2) * rowstride];
        float4 a3 = xp[(t + 3) * rowstride];
        acc.x += a0.x + a1.x + a2.x + a3.x;
        acc.y += a0.y + a1.y + a2.y + a3.y;
        acc.z += a0.z + a1.z + a2.z + a3.z;
        acc.w += a0.w + a1.w + a2.w + a3.w;
    }
    for (; t < n; t++) {
        float4 a0 = xp[t * rowstride];
        acc.x += a0.x; acc.y += a0.y; acc.z += a0.z; acc.w += a0.w;
    }

    // Project this thread's D-lane partial onto the 8 W rows (W L2-resident).
    float po[OUTq];
#pragma unroll
    for (int o = 0; o < OUTq; o++) {
        float4 w = ((const float4*)W)[o * rowstride + tid];
        po[o] = acc.x * w.x + acc.y * w.y + acc.z * w.z + acc.w * w.w;
    }

    // Block-reduce 8 accumulators: warp shuffle, then cross-warp via smem.
#pragma unroll
    for (int o = 0; o < OUTq; o++) {
#pragma unroll
        for (int off = 16; off > 0; off >>= 1)
            po[o] += __shfl_down_sync(0xffffffffu, po[o], off);
    }

    __shared__ float sh[THREADS / 32][OUTq];
    if (lane == 0) {
#pragma unroll
        for (int o = 0; o < OUTq; o++) sh[warp][o] = po[o];
    }
    __syncthreads();

    if (tid < OUTq) {
        float r = 0.f;
#pragma unroll
        for (int w = 0; w < THREADS / 32; w++) r += sh[w][tid];
        g_pout[((b * SPLITS) + s) * OUTq + tid] = r;
    }

    // Make the partial visible, then count this block done for batch b.
    __threadfence();
    __syncthreads();

    __shared__ unsigned s_last;
    if (tid == 0) {
        unsigned prev = atomicInc(&g_count[b], 0xffffffffu);
        s_last = (prev == SPLITS - 1) ? 1u : 0u;
    }
    __syncthreads();

    if (s_last) {
        // Last block for batch b: finalize out[b, :].
        __threadfence();   // acquire: partner writes visible after the atomic
        if (tid < OUTq) {
            float sum = 0.f;
            const float* __restrict__ pp = g_pout + (b * SPLITS) * OUTq + tid;
#pragma unroll
            for (int sp = 0; sp < SPLITS; sp++) sum += pp[sp * OUTq];
            const float inv = 1.0f / (float)len;
            out[b * OUTq + tid] = sum * inv + bias[tid];
        }
        if (tid == 0) g_count[b] = 0;   // reset for next graph replay
    }
}

extern "C" void kernel_launch(void* const* d_in, const int* in_sizes, int n_in,
                              void* d_out, int out_size) {
    const float* x    = (const float*)d_in[0];
    const void*  lens = (const void*)d_in[1];
    const float* W    = (const float*)d_in[2];
    const float* bias = (const float*)d_in[3];
    float* out        = (float*)d_out;

    dim3 grid(Bq, SPLITS);
    fused_kernel<<<grid, THREADS>>>(x, lens, W, bias, out);
}

// round 4
// speedup vs baseline: 1.0423x; 1.0423x over previous
#include <cuda_runtime.h>
#include <cuda_bf16.h>

// EmbeddingsAverage: out[b,o] = (sum_{t<len[b]} x[b,t,:] / len[b]) . W[o,:] + bias[o]
// x: [64, 2048, 1024] f32, lengths: [64] i64-or-i32, W: [8, 1024] f32, bias: [8] f32
// out: [64, 8] f32
// Phase 1: split-T streaming sum + per-block projection onto W -> g_pout.
// Phase 2: tiny finish kernel, launch-latency hidden via PDL (griddepcontrol).

#define Bq   64
#define Tq   2048
#define Dq   1024
#define OUTq 8
#define SPLITS 32
#define ROWS (Tq / SPLITS)   // 64 time rows per split
#define THREADS 256          // 256 * float4 = 1024 = D

// Projected partials per (b, split, out): 64*32*8*4B = 64 KB (L2-resident).
__device__ float g_pout[Bq * SPLITS * OUTq];

// lengths dtype detection: if int64 (little-endian), word[1] is the high word
// of lengths[0] == 0 (lengths <= 2048). If int32, word[1] == lengths[1] >= 1.
__device__ __forceinline__ int load_len(const void* lenp, int b) {
    const unsigned* u = (const unsigned*)lenp;
    if (u[1] == 0u) {
        return (int)u[2 * b];            // int64 layout: low word at 2*b
    } else {
        return (int)((const int*)lenp)[b];
    }
}

__global__ void __launch_bounds__(THREADS)
partial_proj_kernel(const float* __restrict__ x,
                    const void* __restrict__ lenp,
                    const float* __restrict__ W) {
    const int b = blockIdx.x;
    const int s = blockIdx.y;
    const int tid = threadIdx.x;
    const int lane = tid & 31;
    const int warp = tid >> 5;
    const int rowstride = Dq / 4;        // float4 units per time row

    const int len = load_len(lenp, b);
    const int t0 = s * ROWS;
    const int n  = min(t0 + ROWS, len) - t0;   // may be <= 0

    if (n <= 0) {
        // Empty split: zero partial, signal, done.
        if (tid < OUTq)
            g_pout[((b * SPLITS) + s) * OUTq + tid] = 0.f;
        asm volatile("griddepcontrol.launch_dependents;" ::: "memory");
        return;
    }

    float4 acc = make_float4(0.f, 0.f, 0.f, 0.f);

    const float4* __restrict__ xp =
        (const float4*)(x + ((long long)b * Tq + t0) * Dq) + tid;

    int t = 0;
    for (; t + 4 <= n; t += 4) {
        float4 a0 = xp[(t + 0) * rowstride];
        float4 a1 = xp[(t + 1) * rowstride];
        float4 a2 = xp[(t + 2) * rowstride];
        float4 a3 = xp[(t + 3) * rowstride];
        acc.x += a0.x + a1.x + a2.x + a3.x;
        acc.y += a0.y + a1.y + a2.y + a3.y;
        acc.z += a0.z + a1.z + a2.z + a3.z;
        acc.w += a0.w + a1.w + a2.w + a3.w;
    }
    for (; t < n; t++) {
        float4 a0 = xp[t * rowstride];
        acc.x += a0.x; acc.y += a0.y; acc.z += a0.z; acc.w += a0.w;
    }

    // Project this thread's D-lane partial onto the 8 W rows (W L2-resident).
    float po[OUTq];
#pragma unroll
    for (int o = 0; o < OUTq; o++) {
        float4 w = ((const float4*)W)[o * rowstride + tid];
        po[o] = acc.x * w.x + acc.y * w.y + acc.z * w.z + acc.w * w.w;
    }

    // Block-reduce 8 accumulators: warp shuffle, then cross-warp via smem.
#pragma unroll
    for (int o = 0; o < OUTq; o++) {
#pragma unroll
        for (int off = 16; off > 0; off >>= 1)
            po[o] += __shfl_down_sync(0xffffffffu, po[o], off);
    }

    __shared__ float sh[THREADS / 32][OUTq];
    if (lane == 0) {
#pragma unroll
        for (int o = 0; o < OUTq; o++) sh[warp][o] = po[o];
    }
    __syncthreads();

    if (tid < OUTq) {
        float r = 0.f;
#pragma unroll
        for (int w = 0; w < THREADS / 32; w++) r += sh[w][tid];
        g_pout[((b * SPLITS) + s) * OUTq + tid] = r;
    }

    // PDL trigger: writes above are visible to the dependent grid after its
    // griddepcontrol.wait (documented primary->secondary visibility).
    asm volatile("griddepcontrol.launch_dependents;" ::: "memory");
}

// One block: 512 threads = 64 batches x 8 outputs. Reads 64 KB scratch (L2).
__global__ void __launch_bounds__(512)
finish_kernel(const void* __restrict__ lenp,
              const float* __restrict__ bias,
              float* __restrict__ out) {
    asm volatile("griddepcontrol.wait;" ::: "memory");

    const int tid = threadIdx.x;          // tid = b * 8 + o
    const int b = tid >> 3;
    const int o = tid & 7;

    float sum = 0.f;
    const float* __restrict__ pp = g_pout + (b * SPLITS) * OUTq + o;
#pragma unroll
    for (int s = 0; s < SPLITS; s++) sum += pp[s * OUTq];

    const float inv = 1.0f / (float)load_len(lenp, b);
    out[tid] = sum * inv + bias[o];
}

extern "C" void kernel_launch(void* const* d_in, const int* in_sizes, int n_in,
                              void* d_out, int out_size) {
    const float* x    = (const float*)d_in[0];
    const void*  lens = (const void*)d_in[1];
    const float* W    = (const float*)d_in[2];
    const float* bias = (const float*)d_in[3];
    float* out        = (float*)d_out;

    dim3 grid1(Bq, SPLITS);
    partial_proj_kernel<<<grid1, THREADS>>>(x, lens, W);

    // Finish kernel with programmatic dependent launch: comes up concurrently
    // with phase 1, waits in griddepcontrol.wait, runs as phase 1 drains.
    cudaLaunchConfig_t cfg = {};
    cfg.gridDim  = dim3(1, 1, 1);
    cfg.blockDim = dim3(512, 1, 1);
    cfg.dynamicSmemBytes = 0;
    cfg.stream = 0;
    cudaLaunchAttribute attr[1];
    attr[0].id = cudaLaunchAttributeProgrammaticStreamSerialization;
    attr[0].val.programmaticStreamSerializationAllowed = 1;
    cfg.attrs = attr;
    cfg.numAttrs = 1;
    cudaLaunchKernelEx(&cfg, finish_kernel, lens, bias, out);
}